// round 14
// baseline (speedup 1.0000x reference)
#include <cuda_runtime.h>
#include <math.h>

// IDWT 1D (db4), banded synthesis:
//   even j=2i  : L[i+1]*bl1 + L[i]*bl3 + L[i-1]*bl5 + L[i-2]*bl7  (+ H w/ bh)
//   odd  j=2i+1: L[i+2]*bl0 + L[i+1]*bl2 + L[i]*bl4 + L[i-1]*bl6  (+ H w/ bh)
//
// Taps are the fixed db4 synthesis filters as compile-time immediates.
//
// No warp shuffles: each thread loads its halo directly —
//   float2 @ c0-2, float4 @ c0, float2 @ c0+4  (x2 for L and H, 6 LDG total,
// all independent -> MLP 6). Only the first/last thread of each row take
// predicated zero-fill. 8 outputs = 2 float4 streaming stores.

#define BL0  0.23037781330885523f
#define BL1  0.7148465705525415f
#define BL2  0.6308807679295904f
#define BL3 -0.02798376941698385f
#define BL4 -0.18703481171888114f
#define BL5  0.030841381835986965f
#define BL6  0.032883011666982945f
#define BL7 -0.010597401784997278f

#define BH0 -0.010597401784997278f
#define BH1  0.032883011666982945f
#define BH2  0.030841381835986965f
#define BH3  0.18703481171888114f
#define BH4 -0.02798376941698385f
#define BH5 -0.6308807679295904f
#define BH6  0.7148465705525415f
#define BH7 -0.23037781330885523f

__global__ void __launch_bounds__(256)
idwt1d_db4_kernel(const float* __restrict__ L,
                  const float* __restrict__ H,
                  float* __restrict__ out,
                  int Lh)
{
    const int W   = 2 * Lh;
    const int row = blockIdx.y;
    const int nt  = Lh >> 2;                  // threads per row
    const int t   = blockIdx.x * blockDim.x + threadIdx.x;
    if (t >= nt) return;

    const int c0 = 4 * t;                     // thread owns L/H[c0 .. c0+3]

    const float* __restrict__ Lr = L + (size_t)row * Lh;
    const float* __restrict__ Hr = H + (size_t)row * Lh;

    const bool lo_ok = (c0 >= 2);             // false only for thread 0 of row
    const bool hi_ok = (c0 + 4 < Lh);         // false only for last thread

    // All 6 loads independent — issued back-to-back, latency overlapped.
    const float4 l  = *reinterpret_cast<const float4*>(Lr + c0);
    const float4 h  = *reinterpret_cast<const float4*>(Hr + c0);
    float2 llo = make_float2(0.0f, 0.0f), lhi = make_float2(0.0f, 0.0f);
    float2 hlo = make_float2(0.0f, 0.0f), hhi = make_float2(0.0f, 0.0f);
    if (lo_ok) {
        llo = *reinterpret_cast<const float2*>(Lr + c0 - 2);
        hlo = *reinterpret_cast<const float2*>(Hr + c0 - 2);
    }
    if (hi_ok) {
        lhi = *reinterpret_cast<const float2*>(Lr + c0 + 4);
        hhi = *reinterpret_cast<const float2*>(Hr + c0 + 4);
    }

    // la[k] = L[c0-2+k], k=0..7
    const float la[8] = { llo.x, llo.y, l.x, l.y, l.z, l.w, lhi.x, lhi.y };
    const float ha[8] = { hlo.x, hlo.y, h.x, h.y, h.z, h.w, hhi.x, hhi.y };

    float o[8];
#pragma unroll
    for (int m = 0; m < 4; m++) {
        // even j = 2*(c0+m): taps la[m..m+3]
        o[2 * m] =
            fmaf(la[m + 3], BL1, fmaf(la[m + 2], BL3, fmaf(la[m + 1], BL5, la[m] * BL7))) +
            fmaf(ha[m + 3], BH1, fmaf(ha[m + 2], BH3, fmaf(ha[m + 1], BH5, ha[m] * BH7)));
        // odd j = 2*(c0+m)+1: taps la[m+1..m+4]
        o[2 * m + 1] =
            fmaf(la[m + 4], BL0, fmaf(la[m + 3], BL2, fmaf(la[m + 2], BL4, la[m + 1] * BL6))) +
            fmaf(ha[m + 4], BH0, fmaf(ha[m + 3], BH2, fmaf(ha[m + 2], BH4, ha[m + 1] * BH6)));
    }

    float4* op = reinterpret_cast<float4*>(out + (size_t)row * W + 8 * (size_t)t);
    __stcs(op,     make_float4(o[0], o[1], o[2], o[3]));
    __stcs(op + 1, make_float4(o[4], o[5], o[6], o[7]));
}

extern "C" void kernel_launch(void* const* d_in, const int* in_sizes, int n_in,
                              void* d_out, int out_size)
{
    const float* L = (const float*)d_in[0];
    const float* H = (const float*)d_in[1];
    float* out = (float*)d_out;

    long long msz = (long long)in_sizes[2];
    int Lh   = (int)(sqrt((double)(msz / 2)) + 0.5);
    int rows = in_sizes[0] / Lh;              // N*C
    int nt   = Lh >> 2;                       // threads per row

    dim3 block(256);
    dim3 grid((nt + block.x - 1) / block.x, rows);
    idwt1d_db4_kernel<<<grid, block>>>(L, H, out, Lh);
}

// round 16
// speedup vs baseline: 1.0030x; 1.0030x over previous
#include <cuda_runtime.h>
#include <math.h>

// IDWT 1D (db4), banded synthesis:
//   even j=2i  : L[i+1]*bl1 + L[i]*bl3 + L[i-1]*bl5 + L[i-2]*bl7  (+ H w/ bh)
//   odd  j=2i+1: L[i+2]*bl0 + L[i+1]*bl2 + L[i]*bl4 + L[i-1]*bl6  (+ H w/ bh)
// Taps = fixed db4 synthesis filters as compile-time immediates.
//
// Max-parallelism variant: ONE coarse position per thread (2 outputs).
// All loads are SCALAR (i is arbitrary parity, so vector loads would be
// misaligned). 10 independent __ldg per thread (MLP=10), 16 FMA, one
// aligned float2 store.

#define BL0  0.23037781330885523f
#define BL1  0.7148465705525415f
#define BL2  0.6308807679295904f
#define BL3 -0.02798376941698385f
#define BL4 -0.18703481171888114f
#define BL5  0.030841381835986965f
#define BL6  0.032883011666982945f
#define BL7 -0.010597401784997278f

#define BH0 -0.010597401784997278f
#define BH1  0.032883011666982945f
#define BH2  0.030841381835986965f
#define BH3  0.18703481171888114f
#define BH4 -0.02798376941698385f
#define BH5 -0.6308807679295904f
#define BH6  0.7148465705525415f
#define BH7 -0.23037781330885523f

__global__ void __launch_bounds__(256)
idwt1d_db4_kernel(const float* __restrict__ L,
                  const float* __restrict__ H,
                  float* __restrict__ out,
                  int Lh)
{
    const int W   = 2 * Lh;
    const int row = blockIdx.y;
    const int i   = blockIdx.x * blockDim.x + threadIdx.x;   // coarse index
    if (i >= Lh) return;

    const float* __restrict__ Lr = L + (size_t)row * Lh;
    const float* __restrict__ Hr = H + (size_t)row * Lh;

    const bool m2 = (i >= 2);
    const bool m1 = (i >= 1);
    const bool p1 = (i + 1 < Lh);
    const bool p2 = (i + 2 < Lh);

    // 10 independent scalar loads, issued back-to-back (MLP=10).
    const float l0 = __ldg(Lr + i);
    const float h0 = __ldg(Hr + i);
    const float lm2 = m2 ? __ldg(Lr + i - 2) : 0.0f;
    const float hm2 = m2 ? __ldg(Hr + i - 2) : 0.0f;
    const float lm1 = m1 ? __ldg(Lr + i - 1) : 0.0f;
    const float hm1 = m1 ? __ldg(Hr + i - 1) : 0.0f;
    const float lp1 = p1 ? __ldg(Lr + i + 1) : 0.0f;
    const float hp1 = p1 ? __ldg(Hr + i + 1) : 0.0f;
    const float lp2 = p2 ? __ldg(Lr + i + 2) : 0.0f;
    const float hp2 = p2 ? __ldg(Hr + i + 2) : 0.0f;

    // even j = 2i: taps L[i-2..i+1] * (BL7,BL5,BL3,BL1)
    float oe =
        fmaf(lp1, BL1, fmaf(l0, BL3, fmaf(lm1, BL5, lm2 * BL7))) +
        fmaf(hp1, BH1, fmaf(h0, BH3, fmaf(hm1, BH5, hm2 * BH7)));
    // odd j = 2i+1: taps L[i-1..i+2] * (BL6,BL4,BL2,BL0)
    float oo =
        fmaf(lp2, BL0, fmaf(lp1, BL2, fmaf(l0, BL4, lm1 * BL6))) +
        fmaf(hp2, BH0, fmaf(hp1, BH2, fmaf(h0, BH4, hm1 * BH6)));

    // out index 2i is even -> 8-byte aligned float2 store.
    __stcs(reinterpret_cast<float2*>(out + (size_t)row * W + 2 * (size_t)i),
           make_float2(oe, oo));
}

extern "C" void kernel_launch(void* const* d_in, const int* in_sizes, int n_in,
                              void* d_out, int out_size)
{
    const float* L = (const float*)d_in[0];
    const float* H = (const float*)d_in[1];
    float* out = (float*)d_out;

    long long msz = (long long)in_sizes[2];
    int Lh   = (int)(sqrt((double)(msz / 2)) + 0.5);
    int rows = in_sizes[0] / Lh;              // N*C

    dim3 block(256);
    dim3 grid((Lh + block.x - 1) / block.x, rows);
    idwt1d_db4_kernel<<<grid, block>>>(L, H, out, Lh);
}